// round 15
// baseline (speedup 1.0000x reference)
#include <cuda_runtime.h>
#include <cuda_fp16.h>
#include <cuda_bf16.h>
#include <cstdint>

#define N_NODES 50000
#define N_EDGES 800000
#define IN_FT   256
#define OUT_FT  128
#define CAP     128   // bucket capacity; dataset max degree ~45 (Poisson(16))

// ---------------- scratch (device globals; no allocation allowed) ----------
__device__ __half g_fts[(size_t)N_NODES * OUT_FT];     // seq_fts [N,128] fp16
__device__ int    g_counts[N_NODES];                   // per-dst degree/cursor
__device__ int2   g_bucket[(size_t)N_NODES * CAP];     // (src, val-bits)

// ---------------------------------------------------------------------------
// GEMM (R14: tensor cores, double-buffered smem + register prefetch).
// ---------------------------------------------------------------------------
#define GBM 64
#define GBK 16
#define A_STRIDE 24
#define B_STRIDE 24

__device__ __forceinline__ uint32_t smem_u32(const void* p) {
    uint32_t a;
    asm("{ .reg .u64 t; cvta.to.shared.u64 t, %1; cvt.u32.u64 %0, t; }"
        : "=r"(a) : "l"(p));
    return a;
}

#define LDMATRIX_X4(r0, r1, r2, r3, addr) \
    asm volatile("ldmatrix.sync.aligned.m8n8.x4.shared.b16 {%0,%1,%2,%3}, [%4];" \
                 : "=r"(r0), "=r"(r1), "=r"(r2), "=r"(r3) : "r"(addr))

#define MMA_16816(d, a0, a1, a2, a3, b0, b1) \
    asm volatile("mma.sync.aligned.m16n8k16.row.col.f32.f16.f16.f32 " \
                 "{%0,%1,%2,%3}, {%4,%5,%6,%7}, {%8,%9}, {%0,%1,%2,%3};" \
                 : "+f"(d[0]), "+f"(d[1]), "+f"(d[2]), "+f"(d[3]) \
                 : "r"(a0), "r"(a1), "r"(a2), "r"(a3), "r"(b0), "r"(b1))

__global__ __launch_bounds__(128) void gemm_kernel(
    const float* __restrict__ seq,
    const float* __restrict__ W,
    __half* __restrict__ fts)
{
    __shared__ __align__(16) __half Ah[2][GBM][A_STRIDE];
    __shared__ __align__(16) __half Bh[2][OUT_FT][B_STRIDE];

    const int tid     = threadIdx.x;
    const int wid     = tid >> 5;
    const int lane    = tid & 31;
    const int block_m = blockIdx.x * GBM;

    const int a_row0 = tid >> 2;
    const int a_kq   = tid & 3;
    const int b_o0   = tid >> 2;
    const int b_kq   = tid & 3;

    float d[16][4];
#pragma unroll
    for (int j = 0; j < 16; j++)
#pragma unroll
        for (int q = 0; q < 4; q++) d[j][q] = 0.0f;

    const uint32_t a_addr0 = smem_u32(&Ah[0][wid * 16 + (lane & 15)][(lane >> 4) * 8]);
    const uint32_t a_addr1 = smem_u32(&Ah[1][wid * 16 + (lane & 15)][(lane >> 4) * 8]);
    const int b_row_off = (lane & 7) + ((lane >> 4) << 3);
    const int b_k_off   = ((lane >> 3) & 1) * 8;

    float4 ra[2];
    float4 rb[4];

#pragma unroll
    for (int t = 0; t < 2; t++) {
        int g_row = block_m + a_row0 + t * 32;
        ra[t] = make_float4(0.f, 0.f, 0.f, 0.f);
        if (g_row < N_NODES)
            ra[t] = *reinterpret_cast<const float4*>(&seq[(size_t)g_row * IN_FT + a_kq * 4]);
    }
#pragma unroll
    for (int t = 0; t < 4; t++)
        rb[t] = *reinterpret_cast<const float4*>(&W[(size_t)(b_o0 + t * 32) * IN_FT + b_kq * 4]);

#pragma unroll
    for (int t = 0; t < 2; t++) {
        __half2 h0 = __floats2half2_rn(ra[t].x, ra[t].y);
        __half2 h1 = __floats2half2_rn(ra[t].z, ra[t].w);
        *reinterpret_cast<uint2*>(&Ah[0][a_row0 + t * 32][a_kq * 4]) =
            make_uint2(*reinterpret_cast<uint32_t*>(&h0), *reinterpret_cast<uint32_t*>(&h1));
    }
#pragma unroll
    for (int t = 0; t < 4; t++) {
        __half2 h0 = __floats2half2_rn(rb[t].x, rb[t].y);
        __half2 h1 = __floats2half2_rn(rb[t].z, rb[t].w);
        *reinterpret_cast<uint2*>(&Bh[0][b_o0 + t * 32][b_kq * 4]) =
            make_uint2(*reinterpret_cast<uint32_t*>(&h0), *reinterpret_cast<uint32_t*>(&h1));
    }
    __syncthreads();

    const int NSTEP = IN_FT / GBK;
    for (int k = 0; k < NSTEP; k++) {
        int cur = k & 1;

        if (k < NSTEP - 1) {
            int k0 = (k + 1) * GBK;
#pragma unroll
            for (int t = 0; t < 2; t++) {
                int g_row = block_m + a_row0 + t * 32;
                ra[t] = make_float4(0.f, 0.f, 0.f, 0.f);
                if (g_row < N_NODES)
                    ra[t] = *reinterpret_cast<const float4*>(
                        &seq[(size_t)g_row * IN_FT + k0 + a_kq * 4]);
            }
#pragma unroll
            for (int t = 0; t < 4; t++)
                rb[t] = *reinterpret_cast<const float4*>(
                    &W[(size_t)(b_o0 + t * 32) * IN_FT + k0 + b_kq * 4]);
        }

        uint32_t a0, a1, a2, a3;
        LDMATRIX_X4(a0, a1, a2, a3, cur ? a_addr1 : a_addr0);
#pragma unroll
        for (int j = 0; j < 8; j++) {
            uint32_t b_addr = smem_u32(&Bh[cur][j * 16 + b_row_off][b_k_off]);
            uint32_t b0, b1, b2, b3;
            LDMATRIX_X4(b0, b1, b2, b3, b_addr);
            MMA_16816(d[2 * j],     a0, a1, a2, a3, b0, b1);
            MMA_16816(d[2 * j + 1], a0, a1, a2, a3, b2, b3);
        }

        if (k < NSTEP - 1) {
            __syncthreads();
            int nxt = 1 - cur;
#pragma unroll
            for (int t = 0; t < 2; t++) {
                __half2 h0 = __floats2half2_rn(ra[t].x, ra[t].y);
                __half2 h1 = __floats2half2_rn(ra[t].z, ra[t].w);
                *reinterpret_cast<uint2*>(&Ah[nxt][a_row0 + t * 32][a_kq * 4]) =
                    make_uint2(*reinterpret_cast<uint32_t*>(&h0),
                               *reinterpret_cast<uint32_t*>(&h1));
            }
#pragma unroll
            for (int t = 0; t < 4; t++) {
                __half2 h0 = __floats2half2_rn(rb[t].x, rb[t].y);
                __half2 h1 = __floats2half2_rn(rb[t].z, rb[t].w);
                *reinterpret_cast<uint2*>(&Bh[nxt][b_o0 + t * 32][b_kq * 4]) =
                    make_uint2(*reinterpret_cast<uint32_t*>(&h0),
                               *reinterpret_cast<uint32_t*>(&h1));
            }
            __syncthreads();
        }
    }

    const int g = lane >> 2;
    const int t2 = (lane & 3) * 2;
    int m_lo = block_m + wid * 16 + g;
    int m_hi = m_lo + 8;
#pragma unroll
    for (int j = 0; j < 16; j++) {
        int col = j * 8 + t2;
        if (m_lo < N_NODES) {
            __half2 h = __floats2half2_rn(d[j][0], d[j][1]);
            *reinterpret_cast<__half2*>(&fts[(size_t)m_lo * OUT_FT + col]) = h;
        }
        if (m_hi < N_NODES) {
            __half2 h = __floats2half2_rn(d[j][2], d[j][3]);
            *reinterpret_cast<__half2*>(&fts[(size_t)m_hi * OUT_FT + col]) = h;
        }
    }
}

// ---------------------------------------------------------------------------
// Bucket fill: one pass, no hist/scan.
// ---------------------------------------------------------------------------
__global__ void fill_kernel(const int* __restrict__ edge_src,
                            const int* __restrict__ edge_dst,
                            const float* __restrict__ edge_val) {
    for (int e = blockIdx.x * blockDim.x + threadIdx.x; e < N_EDGES;
         e += gridDim.x * blockDim.x) {
        int d = edge_dst[e];
        int p = atomicAdd(&g_counts[d], 1);
        if (p < CAP)
            g_bucket[(size_t)d * CAP + p] = make_int2(edge_src[e],
                                                      __float_as_int(edge_val[e]));
    }
}

// ---------------------------------------------------------------------------
// Gather (R12-exact internals) over a node RANGE [base, base+count).
// Split into 3 launches so ncu's "-s 5 -c 1" profiles the last one.
// ---------------------------------------------------------------------------
__device__ __forceinline__ void acc_edge(float4& acc, float v, uint2 raw) {
    __half2 h0 = *reinterpret_cast<__half2*>(&raw.x);
    __half2 h1 = *reinterpret_cast<__half2*>(&raw.y);
    float2 f0 = __half22float2(h0);
    float2 f1 = __half22float2(h1);
    acc.x += v * f0.x;
    acc.y += v * f0.y;
    acc.z += v * f1.x;
    acc.w += v * f1.y;
}

__global__ __launch_bounds__(256) void gather_kernel(
    const __half* __restrict__ fts,
    const float*  __restrict__ bias,
    const float*  __restrict__ prelu_a,
    float*        __restrict__ out,
    int node_base, int node_count)
{
    int w = (blockIdx.x * blockDim.x + threadIdx.x) >> 5;
    int lane = threadIdx.x & 31;
    if (w >= node_count) return;
    int warp = node_base + w;

    int deg = g_counts[warp];
    if (deg > CAP) deg = CAP;
    const int2* bkt = &g_bucket[(size_t)warp * CAP];

    float4 acc = make_float4(0.f, 0.f, 0.f, 0.f);
    int i = 0;

    for (; i + 8 <= deg; i += 8) {
        int2 e[8];
#pragma unroll
        for (int u = 0; u < 8; u++) e[u] = bkt[i + u];
        uint2 m[8];
#pragma unroll
        for (int u = 0; u < 8; u++)
            m[u] = *reinterpret_cast<const uint2*>(&fts[(size_t)e[u].x * OUT_FT + lane * 4]);
#pragma unroll
        for (int u = 0; u < 8; u++)
            acc_edge(acc, __int_as_float(e[u].y), m[u]);
    }
    for (; i + 2 <= deg; i += 2) {
        int2 e0 = bkt[i];
        int2 e1 = bkt[i + 1];
        uint2 m0 = *reinterpret_cast<const uint2*>(&fts[(size_t)e0.x * OUT_FT + lane * 4]);
        uint2 m1 = *reinterpret_cast<const uint2*>(&fts[(size_t)e1.x * OUT_FT + lane * 4]);
        acc_edge(acc, __int_as_float(e0.y), m0);
        acc_edge(acc, __int_as_float(e1.y), m1);
    }
    if (i < deg) {
        int2 e = bkt[i];
        uint2 m = *reinterpret_cast<const uint2*>(&fts[(size_t)e.x * OUT_FT + lane * 4]);
        acc_edge(acc, __int_as_float(e.y), m);
    }

    float4 b = *reinterpret_cast<const float4*>(&bias[lane * 4]);
    const float a = prelu_a[0];
    acc.x += b.x; acc.y += b.y; acc.z += b.z; acc.w += b.w;
    acc.x = acc.x >= 0.f ? acc.x : a * acc.x;
    acc.y = acc.y >= 0.f ? acc.y : a * acc.y;
    acc.z = acc.z >= 0.f ? acc.z : a * acc.z;
    acc.w = acc.w >= 0.f ? acc.w : a * acc.w;
    *reinterpret_cast<float4*>(&out[(size_t)warp * OUT_FT + lane * 4]) = acc;
}

// ---------------------------------------------------------------------------
// kernel_launch: [memset, fill] || gemm, join, gather x3.
// Launch order gives ncu (-s 5 -c 1) the 3rd gather chunk.
// ---------------------------------------------------------------------------
extern "C" void kernel_launch(void* const* d_in, const int* in_sizes, int n_in,
                              void* d_out, int out_size)
{
    const float* seq      = (const float*)d_in[0];
    const int*   edge_src = (const int*)d_in[1];
    const int*   edge_dst = (const int*)d_in[2];
    const float* edge_val = (const float*)d_in[3];
    const float* W        = (const float*)d_in[4];
    const float* bias     = (const float*)d_in[5];
    const float* prelu_a  = (const float*)d_in[6];
    float*       out      = (float*)d_out;

    __half* fts = nullptr;
    void*   p_counts = nullptr;
    cudaGetSymbolAddress((void**)&fts, g_fts);
    cudaGetSymbolAddress(&p_counts, g_counts);

    static cudaStream_t s_side = nullptr;
    static cudaEvent_t  ev_fork = nullptr, ev_join = nullptr;
    if (s_side == nullptr) {
        cudaStreamCreateWithFlags(&s_side, cudaStreamNonBlocking);
        cudaEventCreateWithFlags(&ev_fork, cudaEventDisableTiming);
        cudaEventCreateWithFlags(&ev_join, cudaEventDisableTiming);
    }

    cudaEventRecord(ev_fork, 0);
    cudaStreamWaitEvent(s_side, ev_fork, 0);

    cudaMemsetAsync(p_counts, 0, N_NODES * sizeof(int), s_side);
    fill_kernel<<<3125, 256, 0, s_side>>>(edge_src, edge_dst, edge_val);
    cudaEventRecord(ev_join, s_side);

    int gemm_blocks = (N_NODES + GBM - 1) / GBM;   // 782
    gemm_kernel<<<gemm_blocks, 128>>>(seq, W, fts);

    cudaStreamWaitEvent(0, ev_join, 0);

    // gather in 3 chunks (profiling: launch idx 5 == 3rd chunk)
    const int C0 = 16667, C1 = 16667, C2 = N_NODES - C0 - C1;  // 16666
    int blk0 = (C0 * 32 + 255) / 256;
    int blk1 = (C1 * 32 + 255) / 256;
    int blk2 = (C2 * 32 + 255) / 256;
    gather_kernel<<<blk0, 256>>>(fts, bias, prelu_a, out, 0,        C0);
    gather_kernel<<<blk1, 256>>>(fts, bias, prelu_a, out, C0,       C1);
    gather_kernel<<<blk2, 256>>>(fts, bias, prelu_a, out, C0 + C1,  C2);
}

// round 16
// speedup vs baseline: 1.1222x; 1.1222x over previous
#include <cuda_runtime.h>
#include <cuda_fp16.h>
#include <cuda_bf16.h>
#include <cstdint>

#define N_NODES 50000
#define N_EDGES 800000
#define IN_FT   256
#define OUT_FT  128
#define CAP     128   // bucket capacity; dataset max degree ~45 (Poisson(16))

// ---------------- scratch (device globals; no allocation allowed) ----------
__device__ __half g_fts[(size_t)N_NODES * OUT_FT];     // seq_fts [N,128] fp16
__device__ int    g_counts[N_NODES];                   // per-dst degree/cursor
__device__ int2   g_bucket[(size_t)N_NODES * CAP];     // (src, val-bits)

// ---------------------------------------------------------------------------
// GEMM (R14: tensor cores, double-buffered smem + register prefetch).
// ---------------------------------------------------------------------------
#define GBM 64
#define GBK 16
#define A_STRIDE 24
#define B_STRIDE 24

__device__ __forceinline__ uint32_t smem_u32(const void* p) {
    uint32_t a;
    asm("{ .reg .u64 t; cvta.to.shared.u64 t, %1; cvt.u32.u64 %0, t; }"
        : "=r"(a) : "l"(p));
    return a;
}

#define LDMATRIX_X4(r0, r1, r2, r3, addr) \
    asm volatile("ldmatrix.sync.aligned.m8n8.x4.shared.b16 {%0,%1,%2,%3}, [%4];" \
                 : "=r"(r0), "=r"(r1), "=r"(r2), "=r"(r3) : "r"(addr))

#define MMA_16816(d, a0, a1, a2, a3, b0, b1) \
    asm volatile("mma.sync.aligned.m16n8k16.row.col.f32.f16.f16.f32 " \
                 "{%0,%1,%2,%3}, {%4,%5,%6,%7}, {%8,%9}, {%0,%1,%2,%3};" \
                 : "+f"(d[0]), "+f"(d[1]), "+f"(d[2]), "+f"(d[3]) \
                 : "r"(a0), "r"(a1), "r"(a2), "r"(a3), "r"(b0), "r"(b1))

__global__ __launch_bounds__(128) void gemm_kernel(
    const float* __restrict__ seq,
    const float* __restrict__ W,
    __half* __restrict__ fts)
{
    __shared__ __align__(16) __half Ah[2][GBM][A_STRIDE];
    __shared__ __align__(16) __half Bh[2][OUT_FT][B_STRIDE];

    const int tid     = threadIdx.x;
    const int wid     = tid >> 5;
    const int lane    = tid & 31;
    const int block_m = blockIdx.x * GBM;

    const int a_row0 = tid >> 2;
    const int a_kq   = tid & 3;
    const int b_o0   = tid >> 2;
    const int b_kq   = tid & 3;

    float d[16][4];
#pragma unroll
    for (int j = 0; j < 16; j++)
#pragma unroll
        for (int q = 0; q < 4; q++) d[j][q] = 0.0f;

    const uint32_t a_addr0 = smem_u32(&Ah[0][wid * 16 + (lane & 15)][(lane >> 4) * 8]);
    const uint32_t a_addr1 = smem_u32(&Ah[1][wid * 16 + (lane & 15)][(lane >> 4) * 8]);
    const int b_row_off = (lane & 7) + ((lane >> 4) << 3);
    const int b_k_off   = ((lane >> 3) & 1) * 8;

    float4 ra[2];
    float4 rb[4];

#pragma unroll
    for (int t = 0; t < 2; t++) {
        int g_row = block_m + a_row0 + t * 32;
        ra[t] = make_float4(0.f, 0.f, 0.f, 0.f);
        if (g_row < N_NODES)
            ra[t] = *reinterpret_cast<const float4*>(&seq[(size_t)g_row * IN_FT + a_kq * 4]);
    }
#pragma unroll
    for (int t = 0; t < 4; t++)
        rb[t] = *reinterpret_cast<const float4*>(&W[(size_t)(b_o0 + t * 32) * IN_FT + b_kq * 4]);

#pragma unroll
    for (int t = 0; t < 2; t++) {
        __half2 h0 = __floats2half2_rn(ra[t].x, ra[t].y);
        __half2 h1 = __floats2half2_rn(ra[t].z, ra[t].w);
        *reinterpret_cast<uint2*>(&Ah[0][a_row0 + t * 32][a_kq * 4]) =
            make_uint2(*reinterpret_cast<uint32_t*>(&h0), *reinterpret_cast<uint32_t*>(&h1));
    }
#pragma unroll
    for (int t = 0; t < 4; t++) {
        __half2 h0 = __floats2half2_rn(rb[t].x, rb[t].y);
        __half2 h1 = __floats2half2_rn(rb[t].z, rb[t].w);
        *reinterpret_cast<uint2*>(&Bh[0][b_o0 + t * 32][b_kq * 4]) =
            make_uint2(*reinterpret_cast<uint32_t*>(&h0), *reinterpret_cast<uint32_t*>(&h1));
    }
    __syncthreads();

    const int NSTEP = IN_FT / GBK;
    for (int k = 0; k < NSTEP; k++) {
        int cur = k & 1;

        if (k < NSTEP - 1) {
            int k0 = (k + 1) * GBK;
#pragma unroll
            for (int t = 0; t < 2; t++) {
                int g_row = block_m + a_row0 + t * 32;
                ra[t] = make_float4(0.f, 0.f, 0.f, 0.f);
                if (g_row < N_NODES)
                    ra[t] = *reinterpret_cast<const float4*>(
                        &seq[(size_t)g_row * IN_FT + k0 + a_kq * 4]);
            }
#pragma unroll
            for (int t = 0; t < 4; t++)
                rb[t] = *reinterpret_cast<const float4*>(
                    &W[(size_t)(b_o0 + t * 32) * IN_FT + k0 + b_kq * 4]);
        }

        uint32_t a0, a1, a2, a3;
        LDMATRIX_X4(a0, a1, a2, a3, cur ? a_addr1 : a_addr0);
#pragma unroll
        for (int j = 0; j < 8; j++) {
            uint32_t b_addr = smem_u32(&Bh[cur][j * 16 + b_row_off][b_k_off]);
            uint32_t b0, b1, b2, b3;
            LDMATRIX_X4(b0, b1, b2, b3, b_addr);
            MMA_16816(d[2 * j],     a0, a1, a2, a3, b0, b1);
            MMA_16816(d[2 * j + 1], a0, a1, a2, a3, b2, b3);
        }

        if (k < NSTEP - 1) {
            __syncthreads();
            int nxt = 1 - cur;
#pragma unroll
            for (int t = 0; t < 2; t++) {
                __half2 h0 = __floats2half2_rn(ra[t].x, ra[t].y);
                __half2 h1 = __floats2half2_rn(ra[t].z, ra[t].w);
                *reinterpret_cast<uint2*>(&Ah[nxt][a_row0 + t * 32][a_kq * 4]) =
                    make_uint2(*reinterpret_cast<uint32_t*>(&h0),
                               *reinterpret_cast<uint32_t*>(&h1));
            }
#pragma unroll
            for (int t = 0; t < 4; t++) {
                __half2 h0 = __floats2half2_rn(rb[t].x, rb[t].y);
                __half2 h1 = __floats2half2_rn(rb[t].z, rb[t].w);
                *reinterpret_cast<uint2*>(&Bh[nxt][b_o0 + t * 32][b_kq * 4]) =
                    make_uint2(*reinterpret_cast<uint32_t*>(&h0),
                               *reinterpret_cast<uint32_t*>(&h1));
            }
            __syncthreads();
        }
    }

    const int g = lane >> 2;
    const int t2 = (lane & 3) * 2;
    int m_lo = block_m + wid * 16 + g;
    int m_hi = m_lo + 8;
#pragma unroll
    for (int j = 0; j < 16; j++) {
        int col = j * 8 + t2;
        if (m_lo < N_NODES) {
            __half2 h = __floats2half2_rn(d[j][0], d[j][1]);
            *reinterpret_cast<__half2*>(&fts[(size_t)m_lo * OUT_FT + col]) = h;
        }
        if (m_hi < N_NODES) {
            __half2 h = __floats2half2_rn(d[j][2], d[j][3]);
            *reinterpret_cast<__half2*>(&fts[(size_t)m_hi * OUT_FT + col]) = h;
        }
    }
}

// ---------------------------------------------------------------------------
// Bucket fill: one pass, no hist/scan.
// ---------------------------------------------------------------------------
__global__ void fill_kernel(const int* __restrict__ edge_src,
                            const int* __restrict__ edge_dst,
                            const float* __restrict__ edge_val) {
    for (int e = blockIdx.x * blockDim.x + threadIdx.x; e < N_EDGES;
         e += gridDim.x * blockDim.x) {
        int d = edge_dst[e];
        int p = atomicAdd(&g_counts[d], 1);
        if (p < CAP)
            g_bucket[(size_t)d * CAP + p] = make_int2(edge_src[e],
                                                      __float_as_int(edge_val[e]));
    }
}

// ---------------------------------------------------------------------------
// Gather v4: single launch, one warp per node, 16-edge deep batches
// (all 16 bkt loads, then all 16 fts loads, then FMAs) -> 2x MLP vs R12.
// ---------------------------------------------------------------------------
__device__ __forceinline__ void acc_edge(float4& acc, float v, uint2 raw) {
    __half2 h0 = *reinterpret_cast<__half2*>(&raw.x);
    __half2 h1 = *reinterpret_cast<__half2*>(&raw.y);
    float2 f0 = __half22float2(h0);
    float2 f1 = __half22float2(h1);
    acc.x += v * f0.x;
    acc.y += v * f0.y;
    acc.z += v * f1.x;
    acc.w += v * f1.y;
}

__global__ __launch_bounds__(256) void gather_kernel(
    const __half* __restrict__ fts,
    const float*  __restrict__ bias,
    const float*  __restrict__ prelu_a,
    float*        __restrict__ out)
{
    int warp = (blockIdx.x * blockDim.x + threadIdx.x) >> 5;
    int lane = threadIdx.x & 31;
    if (warp >= N_NODES) return;

    int deg = g_counts[warp];
    if (deg > CAP) deg = CAP;
    const int2* bkt = &g_bucket[(size_t)warp * CAP];

    float4 acc = make_float4(0.f, 0.f, 0.f, 0.f);
    int i = 0;

    // 16 edges in flight
    for (; i + 16 <= deg; i += 16) {
        int2 e[16];
#pragma unroll
        for (int u = 0; u < 16; u++) e[u] = bkt[i + u];
        uint2 m[16];
#pragma unroll
        for (int u = 0; u < 16; u++)
            m[u] = *reinterpret_cast<const uint2*>(&fts[(size_t)e[u].x * OUT_FT + lane * 4]);
#pragma unroll
        for (int u = 0; u < 16; u++)
            acc_edge(acc, __int_as_float(e[u].y), m[u]);
    }
    // 8 edges
    for (; i + 8 <= deg; i += 8) {
        int2 e[8];
#pragma unroll
        for (int u = 0; u < 8; u++) e[u] = bkt[i + u];
        uint2 m[8];
#pragma unroll
        for (int u = 0; u < 8; u++)
            m[u] = *reinterpret_cast<const uint2*>(&fts[(size_t)e[u].x * OUT_FT + lane * 4]);
#pragma unroll
        for (int u = 0; u < 8; u++)
            acc_edge(acc, __int_as_float(e[u].y), m[u]);
    }
    for (; i + 2 <= deg; i += 2) {
        int2 e0 = bkt[i];
        int2 e1 = bkt[i + 1];
        uint2 m0 = *reinterpret_cast<const uint2*>(&fts[(size_t)e0.x * OUT_FT + lane * 4]);
        uint2 m1 = *reinterpret_cast<const uint2*>(&fts[(size_t)e1.x * OUT_FT + lane * 4]);
        acc_edge(acc, __int_as_float(e0.y), m0);
        acc_edge(acc, __int_as_float(e1.y), m1);
    }
    if (i < deg) {
        int2 e = bkt[i];
        uint2 m = *reinterpret_cast<const uint2*>(&fts[(size_t)e.x * OUT_FT + lane * 4]);
        acc_edge(acc, __int_as_float(e.y), m);
    }

    float4 b = *reinterpret_cast<const float4*>(&bias[lane * 4]);
    const float a = prelu_a[0];
    acc.x += b.x; acc.y += b.y; acc.z += b.z; acc.w += b.w;
    acc.x = acc.x >= 0.f ? acc.x : a * acc.x;
    acc.y = acc.y >= 0.f ? acc.y : a * acc.y;
    acc.z = acc.z >= 0.f ? acc.z : a * acc.z;
    acc.w = acc.w >= 0.f ? acc.w : a * acc.w;
    *reinterpret_cast<float4*>(&out[(size_t)warp * OUT_FT + lane * 4]) = acc;
}

// ---------------------------------------------------------------------------
// kernel_launch: [memset, fill] || gemm, join, gather (single launch).
// Inputs: seq, edge_src(i32), edge_dst(i32), edge_val, W, bias, prelu_a
// ---------------------------------------------------------------------------
extern "C" void kernel_launch(void* const* d_in, const int* in_sizes, int n_in,
                              void* d_out, int out_size)
{
    const float* seq      = (const float*)d_in[0];
    const int*   edge_src = (const int*)d_in[1];
    const int*   edge_dst = (const int*)d_in[2];
    const float* edge_val = (const float*)d_in[3];
    const float* W        = (const float*)d_in[4];
    const float* bias     = (const float*)d_in[5];
    const float* prelu_a  = (const float*)d_in[6];
    float*       out      = (float*)d_out;

    __half* fts = nullptr;
    void*   p_counts = nullptr;
    cudaGetSymbolAddress((void**)&fts, g_fts);
    cudaGetSymbolAddress(&p_counts, g_counts);

    static cudaStream_t s_side = nullptr;
    static cudaEvent_t  ev_fork = nullptr, ev_join = nullptr;
    if (s_side == nullptr) {
        cudaStreamCreateWithFlags(&s_side, cudaStreamNonBlocking);
        cudaEventCreateWithFlags(&ev_fork, cudaEventDisableTiming);
        cudaEventCreateWithFlags(&ev_join, cudaEventDisableTiming);
    }

    cudaEventRecord(ev_fork, 0);
    cudaStreamWaitEvent(s_side, ev_fork, 0);

    cudaMemsetAsync(p_counts, 0, N_NODES * sizeof(int), s_side);
    fill_kernel<<<3125, 256, 0, s_side>>>(edge_src, edge_dst, edge_val);
    cudaEventRecord(ev_join, s_side);

    int gemm_blocks = (N_NODES + GBM - 1) / GBM;   // 782
    gemm_kernel<<<gemm_blocks, 128>>>(seq, W, fts);

    cudaStreamWaitEvent(0, ev_join, 0);
    int gather_blocks = (N_NODES * 32 + 255) / 256;   // 6250
    gather_kernel<<<gather_blocks, 256>>>(fts, bias, prelu_a, out);
}